// round 2
// baseline (speedup 1.0000x reference)
#include <cuda_runtime.h>
#include <cstdint>

// Problem dims (fixed)
#define Tt 4
#define Ll 2048
#define Bb 8
#define Ee 512
#define LB (Ll*Bb)        // 16384
#define Mm (Tt*LB)        // 65536
#define N3 (3*Ee)         // 1536

// Scratch (device globals, allocation-free rule)
static __device__ uint8_t g_spk [(size_t)Mm * N3];   // ~100 MB binary spikes q|k|v
static __device__ float   g_attn[Tt * 64 * 64 * 64]; // 4 MB exact integer counts
static __device__ float   g_s2  [(size_t)Mm * Ee];   // ~134 MB final spikes (0/1 float)

// ---------------------------------------------------------------------------
// Packed fp32x2 helpers (SASS FFMA2 — bitwise-identical IEEE fp32 FMA per lane)
// ---------------------------------------------------------------------------
__device__ __forceinline__ uint64_t pack2(float x, float y) {
    uint64_t r; asm("mov.b64 %0, {%1, %2};" : "=l"(r) : "f"(x), "f"(y)); return r;
}
__device__ __forceinline__ void ffma2(uint64_t& a, uint64_t x, uint64_t y) {
    asm("fma.rn.f32x2 %0, %1, %2, %0;" : "+l"(a) : "l"(x), "l"(y));
}
__device__ __forceinline__ float2 unpack2(uint64_t v) {
    float2 r; asm("mov.b64 {%0, %1}, %2;" : "=f"(r.x), "=f"(r.y) : "l"(v)); return r;
}

// ---------------------------------------------------------------------------
// Fused GEMM1 + LIF:  for each t: proj = query[t] @ W_in^T + b, then LIF(1.0),
// write uint8 spikes. Block 128(lb) x 128(f), 256 threads, 8x8/thread via
// FFMA2 pairs. LIF membrane state lives in smem across the t loop.
// K-ordered fp32 FMA accumulation -> bit-exact vs reference.
// ---------------------------------------------------------------------------
#define SMEM1_FLOATS (2*16*132 + 128*128)
__global__ __launch_bounds__(256, 2) void gemm1_lif_kernel(
    const float* __restrict__ Q,      // (T, LB, E)
    const float* __restrict__ W,      // (N3, E)
    const float* __restrict__ bias)   // (N3)
{
    extern __shared__ float sm[];
    float (*As)[132] = (float (*)[132])sm;
    float (*Ws)[132] = (float (*)[132])(sm + 16*132);
    float* vsm = sm + 2*16*132;       // [128][128] membrane potentials

    const int bm = blockIdx.y * 128;
    const int bn = blockIdx.x * 128;
    const int tid = threadIdx.x;
    const int tx = tid & 15;
    const int ty = tid >> 4;

    // init membrane state (exclusive per thread -> no sync needed)
    #pragma unroll
    for (int i = 0; i < 8; i++)
        #pragma unroll
        for (int j = 0; j < 8; j++)
            vsm[(ty*8 + i)*128 + tx*8 + j] = 0.f;

    for (int t = 0; t < Tt; t++) {
        uint64_t acc[8][4];
        #pragma unroll
        for (int i = 0; i < 8; i++)
            #pragma unroll
            for (int j = 0; j < 4; j++) acc[i][j] = 0ull;

        const float* A = Q + (size_t)t * LB * Ee;

        for (int k0 = 0; k0 < Ee; k0 += 16) {
            __syncthreads();
            for (int i = tid; i < 512; i += 256) {
                int row = i >> 2, c4 = (i & 3) << 2;
                float4 v = *(const float4*)(A + (size_t)(bm + row) * Ee + k0 + c4);
                As[c4+0][row] = v.x; As[c4+1][row] = v.y;
                As[c4+2][row] = v.z; As[c4+3][row] = v.w;
            }
            for (int i = tid; i < 512; i += 256) {
                int row = i >> 2, c4 = (i & 3) << 2;
                float4 v = *(const float4*)(W + (size_t)(bn + row) * Ee + k0 + c4);
                Ws[c4+0][row] = v.x; Ws[c4+1][row] = v.y;
                Ws[c4+2][row] = v.z; Ws[c4+3][row] = v.w;
            }
            __syncthreads();

            #pragma unroll
            for (int kk = 0; kk < 16; kk++) {
                float4 a0 = *(const float4*)&As[kk][ty*8];
                float4 a1 = *(const float4*)&As[kk][ty*8 + 4];
                float4 b0 = *(const float4*)&Ws[kk][tx*8];
                float4 b1 = *(const float4*)&Ws[kk][tx*8 + 4];
                uint64_t B[4] = { pack2(b0.x, b0.y), pack2(b0.z, b0.w),
                                  pack2(b1.x, b1.y), pack2(b1.z, b1.w) };
                float av[8] = {a0.x,a0.y,a0.z,a0.w,a1.x,a1.y,a1.z,a1.w};
                #pragma unroll
                for (int i = 0; i < 8; i++) {
                    uint64_t Ai = pack2(av[i], av[i]);
                    #pragma unroll
                    for (int j = 0; j < 4; j++) ffma2(acc[i][j], Ai, B[j]);
                }
            }
        }

        // Epilogue: bias + LIF(vth=1.0), hard reset, write uint8 spikes
        #pragma unroll
        for (int i = 0; i < 8; i++) {
            uint8_t sp[8];
            #pragma unroll
            for (int j = 0; j < 4; j++) {
                float2 xy = unpack2(acc[i][j]);
                int c0 = tx*8 + j*2;
                float x0 = xy.x + bias[bn + c0];
                float x1 = xy.y + bias[bn + c0 + 1];
                float v0 = vsm[(ty*8 + i)*128 + c0];
                float v1 = vsm[(ty*8 + i)*128 + c0 + 1];
                float h0 = v0 + (x0 - v0) * 0.5f;
                float h1 = v1 + (x1 - v1) * 0.5f;
                bool s0 = (h0 - 1.0f) >= 0.f;
                bool s1 = (h1 - 1.0f) >= 0.f;
                sp[j*2]   = s0 ? 1 : 0;
                sp[j*2+1] = s1 ? 1 : 0;
                vsm[(ty*8 + i)*128 + c0]     = s0 ? 0.f : h0;
                vsm[(ty*8 + i)*128 + c0 + 1] = s1 ? 0.f : h1;
            }
            uchar4 u0 = {sp[0], sp[1], sp[2], sp[3]};
            uchar4 u1 = {sp[4], sp[5], sp[6], sp[7]};
            size_t base = ((size_t)t * LB + bm + ty*8 + i) * N3 + bn + tx*8;
            *(uchar4*)(g_spk + base)     = u0;
            *(uchar4*)(g_spk + base + 4) = u1;
        }
    }
}

// ---------------------------------------------------------------------------
// Generic fp32 GEMM via FFMA2: C[m,n] = sum_k A[m,k]*W[n,k] + bias[n]
// (used for the final out-projection; bit-exact fp32, K-ordered)
// ---------------------------------------------------------------------------
__global__ __launch_bounds__(256) void gemm_bias_f32x2_kernel(
    const float* __restrict__ A, const float* __restrict__ W,
    const float* __restrict__ bias, float* __restrict__ C,
    int M, int N, int K)
{
    __shared__ float As[16][132];
    __shared__ float Ws[16][132];

    const int bm = blockIdx.y * 128;
    const int bn = blockIdx.x * 128;
    const int tid = threadIdx.x;
    const int tx = tid & 15;
    const int ty = tid >> 4;

    uint64_t acc[8][4];
    #pragma unroll
    for (int i = 0; i < 8; i++)
        #pragma unroll
        for (int j = 0; j < 4; j++) acc[i][j] = 0ull;

    for (int k0 = 0; k0 < K; k0 += 16) {
        for (int i = tid; i < 512; i += 256) {
            int row = i >> 2, c4 = (i & 3) << 2;
            float4 v = *(const float4*)(A + (size_t)(bm + row) * K + k0 + c4);
            As[c4+0][row] = v.x; As[c4+1][row] = v.y;
            As[c4+2][row] = v.z; As[c4+3][row] = v.w;
        }
        for (int i = tid; i < 512; i += 256) {
            int row = i >> 2, c4 = (i & 3) << 2;
            float4 v = *(const float4*)(W + (size_t)(bn + row) * K + k0 + c4);
            Ws[c4+0][row] = v.x; Ws[c4+1][row] = v.y;
            Ws[c4+2][row] = v.z; Ws[c4+3][row] = v.w;
        }
        __syncthreads();

        #pragma unroll
        for (int kk = 0; kk < 16; kk++) {
            float4 a0 = *(const float4*)&As[kk][ty*8];
            float4 a1 = *(const float4*)&As[kk][ty*8 + 4];
            float4 b0 = *(const float4*)&Ws[kk][tx*8];
            float4 b1 = *(const float4*)&Ws[kk][tx*8 + 4];
            uint64_t B[4] = { pack2(b0.x, b0.y), pack2(b0.z, b0.w),
                              pack2(b1.x, b1.y), pack2(b1.z, b1.w) };
            float av[8] = {a0.x,a0.y,a0.z,a0.w,a1.x,a1.y,a1.z,a1.w};
            #pragma unroll
            for (int i = 0; i < 8; i++) {
                uint64_t Ai = pack2(av[i], av[i]);
                #pragma unroll
                for (int j = 0; j < 4; j++) ffma2(acc[i][j], Ai, B[j]);
            }
        }
        __syncthreads();
    }

    #pragma unroll
    for (int i = 0; i < 8; i++) {
        int row = bm + ty*8 + i;
        int col = bn + tx*8;
        float o[8];
        #pragma unroll
        for (int j = 0; j < 4; j++) {
            float2 xy = unpack2(acc[i][j]);
            o[j*2]   = xy.x + bias[col + j*2];
            o[j*2+1] = xy.y + bias[col + j*2 + 1];
        }
        *(float4*)(C + (size_t)row * N + col)     = make_float4(o[0],o[1],o[2],o[3]);
        *(float4*)(C + (size_t)row * N + col + 4) = make_float4(o[4],o[5],o[6],o[7]);
    }
}

__global__ __launch_bounds__(256) void zero_attn_kernel()
{
    int i = blockIdx.x * 256 + threadIdx.x;
    g_attn[i] = 0.f;
}

// ---------------------------------------------------------------------------
// attn[t,n,d,e] = sum_l k[t,n,l,d] * v[t,n,l,e]  (binary -> exact int counts)
// Convert uint8->float ONCE at smem fill (was I2F in inner loop).
// grid: (8 lsplit, 64 n, 4 t), block 256 (16x16), 4x4 per thread.
// ---------------------------------------------------------------------------
__global__ __launch_bounds__(256) void kv_attn_kernel()
{
    const int t = blockIdx.z, n = blockIdx.y, ls = blockIdx.x;
    const int b = n >> 3, h = n & 7;
    __shared__ float ks[32][64];
    __shared__ float vs[32][64];
    const int tx = threadIdx.x & 15, ty = threadIdx.x >> 4;

    float acc[4][4];
    #pragma unroll
    for (int i = 0; i < 4; i++)
        #pragma unroll
        for (int j = 0; j < 4; j++) acc[i][j] = 0.f;

    for (int l0 = ls * 256; l0 < ls * 256 + 256; l0 += 32) {
        for (int i = threadIdx.x; i < 512; i += 256) {
            int ll = i >> 4, d4 = (i & 15) << 2;
            size_t base = ((size_t)t * LB + (size_t)(l0 + ll) * Bb + b) * N3 + h * 64 + d4;
            uchar4 kc = *(const uchar4*)(g_spk + base + 512);
            uchar4 vc = *(const uchar4*)(g_spk + base + 1024);
            *(float4*)&ks[ll][d4] = make_float4(kc.x, kc.y, kc.z, kc.w);
            *(float4*)&vs[ll][d4] = make_float4(vc.x, vc.y, vc.z, vc.w);
        }
        __syncthreads();
        #pragma unroll 8
        for (int ll = 0; ll < 32; ll++) {
            float ka[4], va[4];
            #pragma unroll
            for (int i = 0; i < 4; i++) ka[i] = ks[ll][ty*4 + i];
            #pragma unroll
            for (int j = 0; j < 4; j++) va[j] = vs[ll][tx*4 + j];
            #pragma unroll
            for (int i = 0; i < 4; i++)
                #pragma unroll
                for (int j = 0; j < 4; j++) acc[i][j] += ka[i] * va[j];
        }
        __syncthreads();
    }

    float* ap = g_attn + (size_t)(t * 64 + n) * 64 * 64;
    #pragma unroll
    for (int i = 0; i < 4; i++)
        #pragma unroll
        for (int j = 0; j < 4; j++)
            atomicAdd(ap + (ty*4 + i) * 64 + tx*4 + j, acc[i][j]);  // int sums: exact
}

// ---------------------------------------------------------------------------
// out = (q @ attn) * 0.125 -> LIF(0.5) over t, fused. Exact integer math.
// ---------------------------------------------------------------------------
__global__ __launch_bounds__(256) void qattn_lif_kernel()
{
    const int n = blockIdx.y, lt = blockIdx.x;
    const int b = n >> 3, h = n & 7;
    __shared__ float at[64][64];
    __shared__ float qs[64][64];
    const int e = threadIdx.x & 63, lr = threadIdx.x >> 6;

    float vmem[16];
    #pragma unroll
    for (int i = 0; i < 16; i++) vmem[i] = 0.f;

    for (int t = 0; t < Tt; t++) {
        __syncthreads();
        for (int i = threadIdx.x; i < 4096; i += 256)
            at[i >> 6][i & 63] = g_attn[(size_t)(t * 64 + n) * 4096 + i];
        for (int i = threadIdx.x; i < 1024; i += 256) {
            int ll = i >> 4, d4 = (i & 15) << 2;
            size_t base = ((size_t)t * LB + (size_t)(lt * 64 + ll) * Bb + b) * N3 + h * 64 + d4;
            uchar4 qc = *(const uchar4*)(g_spk + base);
            *(float4*)&qs[ll][d4] = make_float4(qc.x, qc.y, qc.z, qc.w);
        }
        __syncthreads();

        #pragma unroll
        for (int li = 0; li < 16; li++) {
            int llocal = li * 4 + lr;
            float s = 0.f;
            #pragma unroll
            for (int d = 0; d < 64; d++)
                s += qs[llocal][d] * at[d][e];
            float x = s * 0.125f;                       // exact
            float hh = vmem[li] + (x - vmem[li]) * 0.5f;
            bool sp = (hh - 0.5f) >= 0.f;
            int l = lt * 64 + llocal;
            g_s2[(((size_t)t * Ll + l) * Bb + b) * Ee + h * 64 + e] = sp ? 1.f : 0.f;
            vmem[li] = sp ? 0.f : hh;
        }
    }
}

// ---------------------------------------------------------------------------
extern "C" void kernel_launch(void* const* d_in, const int* in_sizes, int n_in,
                              void* d_out, int out_size)
{
    const float* query = (const float*)d_in[0];   // (T,L,B,E)
    const float* w_in  = (const float*)d_in[1];   // (3E, E)
    const float* b_in  = (const float*)d_in[2];   // (3E)
    const float* w_out = (const float*)d_in[3];   // (E, E)
    const float* b_out = (const float*)d_in[4];   // (E)
    float* out = (float*)d_out;                   // (T,L,B,E)

    void* p_s2 = nullptr;
    cudaGetSymbolAddress(&p_s2, g_s2);

    // 1) fused proj + LIF -> binary spikes (eliminates g_proj round-trip)
    static const int SMEM1 = SMEM1_FLOATS * 4;
    cudaFuncSetAttribute(gemm1_lif_kernel,
                         cudaFuncAttributeMaxDynamicSharedMemorySize, SMEM1);
    gemm1_lif_kernel<<<dim3(N3 / 128, LB / 128), 256, SMEM1>>>(query, w_in, b_in);

    // 2) attn = k^T v per (t, head)
    zero_attn_kernel<<<(Tt * 64 * 64 * 64) / 256, 256>>>();
    kv_attn_kernel<<<dim3(8, 64, Tt), 256>>>();

    // 3) out = q @ attn * 0.125 -> LIF(0.5) -> s2 spikes
    qattn_lif_kernel<<<dim3(Ll / 64, 64), 256>>>();

    // 4) final = s2 @ W_out^T + b_out
    gemm_bias_f32x2_kernel<<<dim3(Ee / 128, Mm / 128), 256>>>(
        (const float*)p_s2, w_out, b_out, out, Mm, Ee, Ee);
}

// round 3
// speedup vs baseline: 1.1281x; 1.1281x over previous
#include <cuda_runtime.h>
#include <cuda_bf16.h>
#include <cstdint>

// Problem dims (fixed)
#define Tt 4
#define Ll 2048
#define Bb 8
#define Ee 512
#define LB (Ll*Bb)        // 16384
#define Mm (Tt*LB)        // 65536
#define N3 (3*Ee)         // 1536

// Scratch (device globals, allocation-free rule)
static __device__ uint8_t        g_spk [(size_t)Mm * N3];   // ~100 MB qkv spikes
static __device__ float          g_attn[Tt * 64 * 64 * 64]; // 4 MB exact counts
static __device__ __nv_bfloat16  g_s2  [(size_t)Mm * Ee];   // 67 MB s2 spikes (bf16 0/1)
static __device__ __nv_bfloat16  g_whi [Ee * Ee];           // W_out hi split
static __device__ __nv_bfloat16  g_wlo [Ee * Ee];           // W_out lo split

// ---------------------------------------------------------------------------
// Fused GEMM1 + LIF: for each t: proj = query[t] @ W_in^T + b -> LIF(1.0) ->
// uint8 spikes. 128x128 tile, 256 thr, 8x8/thread, plain FFMA (bit-exact,
// K-ordered). Membrane state in smem across the t loop.
// ---------------------------------------------------------------------------
#define SMEM1_FLOATS (2*16*132 + 128*128)
__global__ __launch_bounds__(256, 2) void gemm1_lif_kernel(
    const float* __restrict__ Q,      // (T, LB, E)
    const float* __restrict__ W,      // (N3, E)
    const float* __restrict__ bias)   // (N3)
{
    extern __shared__ float sm[];
    float (*As)[132] = (float (*)[132])sm;
    float (*Ws)[132] = (float (*)[132])(sm + 16*132);
    float* vsm = sm + 2*16*132;       // [128][128] membrane potentials

    const int bm = blockIdx.y * 128;
    const int bn = blockIdx.x * 128;
    const int tid = threadIdx.x;
    const int tx = tid & 15;
    const int ty = tid >> 4;

    // per-thread bias cache (cols fixed across t)
    float bc[8];
    #pragma unroll
    for (int j = 0; j < 8; j++) bc[j] = bias[bn + tx*8 + j];

    // init membrane state (exclusive per thread)
    #pragma unroll
    for (int i = 0; i < 8; i++)
        #pragma unroll
        for (int j = 0; j < 8; j++)
            vsm[(ty*8 + i)*128 + tx*8 + j] = 0.f;

    for (int t = 0; t < Tt; t++) {
        float acc[8][8];
        #pragma unroll
        for (int i = 0; i < 8; i++)
            #pragma unroll
            for (int j = 0; j < 8; j++) acc[i][j] = 0.f;

        const float* A = Q + (size_t)t * LB * Ee;

        for (int k0 = 0; k0 < Ee; k0 += 16) {
            __syncthreads();
            for (int i = tid; i < 512; i += 256) {
                int row = i >> 2, c4 = (i & 3) << 2;
                float4 v = *(const float4*)(A + (size_t)(bm + row) * Ee + k0 + c4);
                As[c4+0][row] = v.x; As[c4+1][row] = v.y;
                As[c4+2][row] = v.z; As[c4+3][row] = v.w;
            }
            for (int i = tid; i < 512; i += 256) {
                int row = i >> 2, c4 = (i & 3) << 2;
                float4 v = *(const float4*)(W + (size_t)(bn + row) * Ee + k0 + c4);
                Ws[c4+0][row] = v.x; Ws[c4+1][row] = v.y;
                Ws[c4+2][row] = v.z; Ws[c4+3][row] = v.w;
            }
            __syncthreads();

            #pragma unroll
            for (int kk = 0; kk < 16; kk++) {
                float a[8], b[8];
                float4 a0 = *(const float4*)&As[kk][ty*8];
                float4 a1 = *(const float4*)&As[kk][ty*8 + 4];
                float4 b0 = *(const float4*)&Ws[kk][tx*8];
                float4 b1 = *(const float4*)&Ws[kk][tx*8 + 4];
                a[0]=a0.x;a[1]=a0.y;a[2]=a0.z;a[3]=a0.w;a[4]=a1.x;a[5]=a1.y;a[6]=a1.z;a[7]=a1.w;
                b[0]=b0.x;b[1]=b0.y;b[2]=b0.z;b[3]=b0.w;b[4]=b1.x;b[5]=b1.y;b[6]=b1.z;b[7]=b1.w;
                #pragma unroll
                for (int i = 0; i < 8; i++)
                    #pragma unroll
                    for (int j = 0; j < 8; j++) acc[i][j] += a[i] * b[j];
            }
        }

        // Epilogue: bias + LIF(vth=1.0), hard reset, write uint8 spikes
        #pragma unroll
        for (int i = 0; i < 8; i++) {
            uint8_t sp[8];
            #pragma unroll
            for (int j = 0; j < 8; j++) {
                float x = acc[i][j] + bc[j];
                float v = vsm[(ty*8 + i)*128 + tx*8 + j];
                float h = v + (x - v) * 0.5f;
                bool s = (h - 1.0f) >= 0.f;
                sp[j] = s ? 1 : 0;
                vsm[(ty*8 + i)*128 + tx*8 + j] = s ? 0.f : h;
            }
            uchar4 u0 = {sp[0], sp[1], sp[2], sp[3]};
            uchar4 u1 = {sp[4], sp[5], sp[6], sp[7]};
            size_t base = ((size_t)t * LB + bm + ty*8 + i) * N3 + bn + tx*8;
            *(uchar4*)(g_spk + base)     = u0;
            *(uchar4*)(g_spk + base + 4) = u1;
        }
    }
}

__global__ __launch_bounds__(256) void zero_attn_kernel()
{
    int i = blockIdx.x * 256 + threadIdx.x;
    g_attn[i] = 0.f;
}

// ---------------------------------------------------------------------------
// attn[t,n,d,e] = sum_l k[t,n,l,d] * v[t,n,l,e]  (binary -> exact counts)
// ---------------------------------------------------------------------------
__global__ __launch_bounds__(256) void kv_attn_kernel()
{
    const int t = blockIdx.z, n = blockIdx.y, ls = blockIdx.x;
    const int b = n >> 3, h = n & 7;
    __shared__ float ks[32][64];
    __shared__ float vs[32][64];
    const int tx = threadIdx.x & 15, ty = threadIdx.x >> 4;

    float acc[4][4];
    #pragma unroll
    for (int i = 0; i < 4; i++)
        #pragma unroll
        for (int j = 0; j < 4; j++) acc[i][j] = 0.f;

    for (int l0 = ls * 256; l0 < ls * 256 + 256; l0 += 32) {
        for (int i = threadIdx.x; i < 512; i += 256) {
            int ll = i >> 4, d4 = (i & 15) << 2;
            size_t base = ((size_t)t * LB + (size_t)(l0 + ll) * Bb + b) * N3 + h * 64 + d4;
            uchar4 kc = *(const uchar4*)(g_spk + base + 512);
            uchar4 vc = *(const uchar4*)(g_spk + base + 1024);
            *(float4*)&ks[ll][d4] = make_float4(kc.x, kc.y, kc.z, kc.w);
            *(float4*)&vs[ll][d4] = make_float4(vc.x, vc.y, vc.z, vc.w);
        }
        __syncthreads();
        #pragma unroll 8
        for (int ll = 0; ll < 32; ll++) {
            float ka[4], va[4];
            #pragma unroll
            for (int i = 0; i < 4; i++) ka[i] = ks[ll][ty*4 + i];
            #pragma unroll
            for (int j = 0; j < 4; j++) va[j] = vs[ll][tx*4 + j];
            #pragma unroll
            for (int i = 0; i < 4; i++)
                #pragma unroll
                for (int j = 0; j < 4; j++) acc[i][j] += ka[i] * va[j];
        }
        __syncthreads();
    }

    float* ap = g_attn + (size_t)(t * 64 + n) * 64 * 64;
    #pragma unroll
    for (int i = 0; i < 4; i++)
        #pragma unroll
        for (int j = 0; j < 4; j++)
            atomicAdd(ap + (ty*4 + i) * 64 + tx*4 + j, acc[i][j]);  // int sums: exact
}

// ---------------------------------------------------------------------------
// out = (q @ attn) * 0.125 -> LIF(0.5) over t, fused. Exact integer math.
// Writes bf16 0/1 spikes for the tensor-core out-projection.
// ---------------------------------------------------------------------------
__global__ __launch_bounds__(256) void qattn_lif_kernel()
{
    const int n = blockIdx.y, lt = blockIdx.x;
    const int b = n >> 3, h = n & 7;
    __shared__ float   at[64][64];
    __shared__ uint8_t qs[64][64];
    const int e = threadIdx.x & 63, lr = threadIdx.x >> 6;

    float vmem[16];
    #pragma unroll
    for (int i = 0; i < 16; i++) vmem[i] = 0.f;

    for (int t = 0; t < Tt; t++) {
        __syncthreads();
        for (int i = threadIdx.x; i < 4096; i += 256)
            at[i >> 6][i & 63] = g_attn[(size_t)(t * 64 + n) * 4096 + i];
        for (int i = threadIdx.x; i < 1024; i += 256) {
            int ll = i >> 4, d4 = (i & 15) << 2;
            size_t base = ((size_t)t * LB + (size_t)(lt * 64 + ll) * Bb + b) * N3 + h * 64 + d4;
            *(uchar4*)&qs[ll][d4] = *(const uchar4*)(g_spk + base);
        }
        __syncthreads();

        #pragma unroll
        for (int li = 0; li < 16; li++) {
            int llocal = li * 4 + lr;
            float s = 0.f;
            #pragma unroll
            for (int d = 0; d < 64; d++)
                s += (float)qs[llocal][d] * at[d][e];
            float x = s * 0.125f;                       // exact
            float hh = vmem[li] + (x - vmem[li]) * 0.5f;
            bool sp = (hh - 0.5f) >= 0.f;
            int l = lt * 64 + llocal;
            g_s2[(((size_t)t * Ll + l) * Bb + b) * Ee + h * 64 + e] =
                __float2bfloat16(sp ? 1.f : 0.f);
            vmem[li] = sp ? 0.f : hh;
        }
    }
}

// ---------------------------------------------------------------------------
// Split W_out into bf16 hi + bf16 lo (exact to ~2^-16 relative)
// ---------------------------------------------------------------------------
__global__ __launch_bounds__(256) void wsplit_kernel(const float* __restrict__ W)
{
    int i = blockIdx.x * 256 + threadIdx.x;     // over Ee*Ee
    float w = W[i];
    __nv_bfloat16 hi = __float2bfloat16(w);
    float r = w - __bfloat162float(hi);
    g_whi[i] = hi;
    g_wlo[i] = __float2bfloat16(r);
}

// ---------------------------------------------------------------------------
// GEMM5 on tensor cores: out = s2 @ (Whi + Wlo)^T + bias, fp32 accumulate.
// s2 is binary -> exact in bf16; Whi/Wlo products exact; total err ~1.5e-5.
// Block 128x128, 8 warps (4m x 2n), each warp 32x64 via mma.m16n8k16.
// ---------------------------------------------------------------------------
__global__ __launch_bounds__(256) void gemm5_mma_kernel(
    const float* __restrict__ bias, float* __restrict__ C)
{
    __shared__ __nv_bfloat16 As [128][40];
    __shared__ __nv_bfloat16 Bhi[128][40];
    __shared__ __nv_bfloat16 Blo[128][40];

    const int bm = blockIdx.y * 128;
    const int bn = blockIdx.x * 128;
    const int tid  = threadIdx.x;
    const int wid  = tid >> 5;
    const int lane = tid & 31;
    const int wm = wid >> 1;          // 0..3 -> 32-row band
    const int wn = wid & 1;           // 0..1 -> 64-col band
    const int lr = lane >> 2;         // 0..7
    const int lc = (lane & 3) * 2;    // 0,2,4,6

    float acc[2][8][4];
    #pragma unroll
    for (int mi = 0; mi < 2; mi++)
        #pragma unroll
        for (int ni = 0; ni < 8; ni++)
            #pragma unroll
            for (int r = 0; r < 4; r++) acc[mi][ni][r] = 0.f;

    for (int k0 = 0; k0 < Ee; k0 += 32) {
        // load tiles: 128 rows x 32 bf16 each = 512 x (8 bf16) vectors
        for (int i = tid; i < 512; i += 256) {
            int row = i >> 2, c8 = (i & 3) << 3;
            *(uint4*)&As[row][c8] =
                *(const uint4*)(g_s2 + (size_t)(bm + row) * Ee + k0 + c8);
        }
        for (int i = tid; i < 512; i += 256) {
            int row = i >> 2, c8 = (i & 3) << 3;
            size_t off = (size_t)(bn + row) * Ee + k0 + c8;
            *(uint4*)&Bhi[row][c8] = *(const uint4*)(g_whi + off);
            *(uint4*)&Blo[row][c8] = *(const uint4*)(g_wlo + off);
        }
        __syncthreads();

        #pragma unroll
        for (int kk = 0; kk < 32; kk += 16) {
            // A fragments for 2 m16 tiles
            uint32_t a[2][4];
            #pragma unroll
            for (int mi = 0; mi < 2; mi++) {
                int rbase = wm*32 + mi*16;
                a[mi][0] = *(const uint32_t*)&As[rbase + lr    ][kk + lc    ];
                a[mi][1] = *(const uint32_t*)&As[rbase + lr + 8][kk + lc    ];
                a[mi][2] = *(const uint32_t*)&As[rbase + lr    ][kk + lc + 8];
                a[mi][3] = *(const uint32_t*)&As[rbase + lr + 8][kk + lc + 8];
            }
            #pragma unroll
            for (int ni = 0; ni < 8; ni++) {
                int nrow = wn*64 + ni*8 + lr;
                uint32_t bh0 = *(const uint32_t*)&Bhi[nrow][kk + lc];
                uint32_t bh1 = *(const uint32_t*)&Bhi[nrow][kk + lc + 8];
                uint32_t bl0 = *(const uint32_t*)&Blo[nrow][kk + lc];
                uint32_t bl1 = *(const uint32_t*)&Blo[nrow][kk + lc + 8];
                #pragma unroll
                for (int mi = 0; mi < 2; mi++) {
                    asm volatile(
                        "mma.sync.aligned.m16n8k16.row.col.f32.bf16.bf16.f32 "
                        "{%0,%1,%2,%3}, {%4,%5,%6,%7}, {%8,%9}, {%0,%1,%2,%3};"
                        : "+f"(acc[mi][ni][0]), "+f"(acc[mi][ni][1]),
                          "+f"(acc[mi][ni][2]), "+f"(acc[mi][ni][3])
                        : "r"(a[mi][0]), "r"(a[mi][1]), "r"(a[mi][2]), "r"(a[mi][3]),
                          "r"(bh0), "r"(bh1));
                    asm volatile(
                        "mma.sync.aligned.m16n8k16.row.col.f32.bf16.bf16.f32 "
                        "{%0,%1,%2,%3}, {%4,%5,%6,%7}, {%8,%9}, {%0,%1,%2,%3};"
                        : "+f"(acc[mi][ni][0]), "+f"(acc[mi][ni][1]),
                          "+f"(acc[mi][ni][2]), "+f"(acc[mi][ni][3])
                        : "r"(a[mi][0]), "r"(a[mi][1]), "r"(a[mi][2]), "r"(a[mi][3]),
                          "r"(bl0), "r"(bl1));
                }
            }
        }
        __syncthreads();
    }

    // Epilogue: bias + store fp32
    #pragma unroll
    for (int mi = 0; mi < 2; mi++) {
        #pragma unroll
        for (int ni = 0; ni < 8; ni++) {
            int col = bn + wn*64 + ni*8 + lc;
            float b0 = bias[col], b1 = bias[col + 1];
            int row0 = bm + wm*32 + mi*16 + lr;
            float2 o0 = make_float2(acc[mi][ni][0] + b0, acc[mi][ni][1] + b1);
            float2 o1 = make_float2(acc[mi][ni][2] + b0, acc[mi][ni][3] + b1);
            *(float2*)(C + (size_t)row0 * Ee + col)       = o0;
            *(float2*)(C + (size_t)(row0 + 8) * Ee + col) = o1;
        }
    }
}

// ---------------------------------------------------------------------------
extern "C" void kernel_launch(void* const* d_in, const int* in_sizes, int n_in,
                              void* d_out, int out_size)
{
    const float* query = (const float*)d_in[0];   // (T,L,B,E)
    const float* w_in  = (const float*)d_in[1];   // (3E, E)
    const float* b_in  = (const float*)d_in[2];   // (3E)
    const float* w_out = (const float*)d_in[3];   // (E, E)
    const float* b_out = (const float*)d_in[4];   // (E)
    float* out = (float*)d_out;                   // (T,L,B,E)

    // 1) fused proj + LIF -> binary spikes
    static const int SMEM1 = SMEM1_FLOATS * 4;
    cudaFuncSetAttribute(gemm1_lif_kernel,
                         cudaFuncAttributeMaxDynamicSharedMemorySize, SMEM1);
    gemm1_lif_kernel<<<dim3(N3 / 128, LB / 128), 256, SMEM1>>>(query, w_in, b_in);

    // W_out split (independent of step 1/2 — overlaps)
    wsplit_kernel<<<(Ee * Ee) / 256, 256>>>(w_out);

    // 2) attn = k^T v per (t, head)
    zero_attn_kernel<<<(Tt * 64 * 64 * 64) / 256, 256>>>();
    kv_attn_kernel<<<dim3(8, 64, Tt), 256>>>();

    // 3) out = q @ attn * 0.125 -> LIF(0.5) -> s2 spikes (bf16)
    qattn_lif_kernel<<<dim3(Ll / 64, 64), 256>>>();

    // 4) final = s2 @ W_out^T + b_out on tensor cores (hi/lo bf16 split)
    gemm5_mma_kernel<<<dim3(Ee / 128, Mm / 128), 256>>>(b_out, out);
}

// round 4
// speedup vs baseline: 1.7557x; 1.5564x over previous
#include <cuda_runtime.h>
#include <cuda_bf16.h>
#include <cstdint>

// Problem dims (fixed)
#define Tt 4
#define Ll 2048
#define Bb 8
#define Ee 512
#define LB (Ll*Bb)        // 16384
#define Mm (Tt*LB)        // 65536
#define N3 (3*Ee)         // 1536
#define FIX_CAP (1u<<20)
#define DELTA 3e-3f

// Scratch (device globals, allocation-free rule)
static __device__ float          g_proj[(size_t)Mm * N3];   // 402 MB fast proj
static __device__ __nv_bfloat16  g_a0  [(size_t)Mm * Ee];   // 67 MB query hi
static __device__ __nv_bfloat16  g_a1  [(size_t)Mm * Ee];   // 67 MB query lo
static __device__ __nv_bfloat16  g_w0  [N3 * Ee];           // W_in hi
static __device__ __nv_bfloat16  g_w1  [N3 * Ee];           // W_in lo
static __device__ uint8_t        g_spk [(size_t)Mm * N3];   // 100 MB qkv spikes
static __device__ float          g_attn[Tt * 64 * 64 * 64]; // 4 MB exact counts
static __device__ __nv_bfloat16  g_s2  [(size_t)Mm * Ee];   // 67 MB s2 spikes
static __device__ __nv_bfloat16  g_whi [Ee * Ee];           // W_out hi
static __device__ __nv_bfloat16  g_wlo [Ee * Ee];           // W_out lo
static __device__ unsigned int   g_nflag;
static __device__ unsigned int   g_list[FIX_CAP];

// ---------------------------------------------------------------------------
// bf16 hi/lo split helpers
// ---------------------------------------------------------------------------
__global__ __launch_bounds__(256) void split_kernel(
    const float* __restrict__ src, __nv_bfloat16* __restrict__ d0,
    __nv_bfloat16* __restrict__ d1)
{
    size_t i4 = ((size_t)blockIdx.x * 256 + threadIdx.x) * 4;
    float4 v = *(const float4*)(src + i4);
    float x[4] = {v.x, v.y, v.z, v.w};
    __nv_bfloat16 h[4], l[4];
    #pragma unroll
    for (int j = 0; j < 4; j++) {
        h[j] = __float2bfloat16(x[j]);
        l[j] = __float2bfloat16(x[j] - __bfloat162float(h[j]));
    }
    *(uint2*)(d0 + i4) = *(uint2*)h;
    *(uint2*)(d1 + i4) = *(uint2*)l;
}

__global__ void zero_flag_kernel() { g_nflag = 0u; }

// ---------------------------------------------------------------------------
// GEMM1 fast path on tensor cores: proj = q @ W_in^T + bias via bf16 2-split,
// 3 product passes (a0w0 + a1w0 + a0w1), fp32 accumulate.
// Block 128x128, 8 warps (4m x 2n). Fragment layout cloned from R3 gemm5
// (verified correct by rel_err 2.47e-6).
// ---------------------------------------------------------------------------
__global__ __launch_bounds__(256) void gemm1_fast_kernel(
    const float* __restrict__ bias)
{
    __shared__ __nv_bfloat16 A0s[128][40];
    __shared__ __nv_bfloat16 A1s[128][40];
    __shared__ __nv_bfloat16 B0s[128][40];
    __shared__ __nv_bfloat16 B1s[128][40];

    const int bm = blockIdx.y * 128;
    const int bn = blockIdx.x * 128;
    const int tid  = threadIdx.x;
    const int wid  = tid >> 5;
    const int lane = tid & 31;
    const int wm = wid >> 1;
    const int wn = wid & 1;
    const int lr = lane >> 2;
    const int lc = (lane & 3) * 2;

    float acc[2][8][4];
    #pragma unroll
    for (int mi = 0; mi < 2; mi++)
        #pragma unroll
        for (int ni = 0; ni < 8; ni++)
            #pragma unroll
            for (int r = 0; r < 4; r++) acc[mi][ni][r] = 0.f;

    for (int k0 = 0; k0 < Ee; k0 += 32) {
        for (int i = tid; i < 512; i += 256) {
            int row = i >> 2, c8 = (i & 3) << 3;
            size_t offa = (size_t)(bm + row) * Ee + k0 + c8;
            *(uint4*)&A0s[row][c8] = *(const uint4*)(g_a0 + offa);
            *(uint4*)&A1s[row][c8] = *(const uint4*)(g_a1 + offa);
            size_t offb = (size_t)(bn + row) * Ee + k0 + c8;
            *(uint4*)&B0s[row][c8] = *(const uint4*)(g_w0 + offb);
            *(uint4*)&B1s[row][c8] = *(const uint4*)(g_w1 + offb);
        }
        __syncthreads();

        #pragma unroll
        for (int kk = 0; kk < 32; kk += 16) {
            uint32_t a0[2][4], a1[2][4];
            #pragma unroll
            for (int mi = 0; mi < 2; mi++) {
                int rb = wm*32 + mi*16;
                a0[mi][0] = *(const uint32_t*)&A0s[rb + lr    ][kk + lc    ];
                a0[mi][1] = *(const uint32_t*)&A0s[rb + lr + 8][kk + lc    ];
                a0[mi][2] = *(const uint32_t*)&A0s[rb + lr    ][kk + lc + 8];
                a0[mi][3] = *(const uint32_t*)&A0s[rb + lr + 8][kk + lc + 8];
                a1[mi][0] = *(const uint32_t*)&A1s[rb + lr    ][kk + lc    ];
                a1[mi][1] = *(const uint32_t*)&A1s[rb + lr + 8][kk + lc    ];
                a1[mi][2] = *(const uint32_t*)&A1s[rb + lr    ][kk + lc + 8];
                a1[mi][3] = *(const uint32_t*)&A1s[rb + lr + 8][kk + lc + 8];
            }
            #pragma unroll
            for (int ni = 0; ni < 8; ni++) {
                int nrow = wn*64 + ni*8 + lr;
                uint32_t w00 = *(const uint32_t*)&B0s[nrow][kk + lc];
                uint32_t w01 = *(const uint32_t*)&B0s[nrow][kk + lc + 8];
                uint32_t w10 = *(const uint32_t*)&B1s[nrow][kk + lc];
                uint32_t w11 = *(const uint32_t*)&B1s[nrow][kk + lc + 8];
                #pragma unroll
                for (int mi = 0; mi < 2; mi++) {
                    asm volatile(
                        "mma.sync.aligned.m16n8k16.row.col.f32.bf16.bf16.f32 "
                        "{%0,%1,%2,%3}, {%4,%5,%6,%7}, {%8,%9}, {%0,%1,%2,%3};"
                        : "+f"(acc[mi][ni][0]), "+f"(acc[mi][ni][1]),
                          "+f"(acc[mi][ni][2]), "+f"(acc[mi][ni][3])
                        : "r"(a0[mi][0]), "r"(a0[mi][1]), "r"(a0[mi][2]), "r"(a0[mi][3]),
                          "r"(w00), "r"(w01));
                    asm volatile(
                        "mma.sync.aligned.m16n8k16.row.col.f32.bf16.bf16.f32 "
                        "{%0,%1,%2,%3}, {%4,%5,%6,%7}, {%8,%9}, {%0,%1,%2,%3};"
                        : "+f"(acc[mi][ni][0]), "+f"(acc[mi][ni][1]),
                          "+f"(acc[mi][ni][2]), "+f"(acc[mi][ni][3])
                        : "r"(a1[mi][0]), "r"(a1[mi][1]), "r"(a1[mi][2]), "r"(a1[mi][3]),
                          "r"(w00), "r"(w01));
                    asm volatile(
                        "mma.sync.aligned.m16n8k16.row.col.f32.bf16.bf16.f32 "
                        "{%0,%1,%2,%3}, {%4,%5,%6,%7}, {%8,%9}, {%0,%1,%2,%3};"
                        : "+f"(acc[mi][ni][0]), "+f"(acc[mi][ni][1]),
                          "+f"(acc[mi][ni][2]), "+f"(acc[mi][ni][3])
                        : "r"(a0[mi][0]), "r"(a0[mi][1]), "r"(a0[mi][2]), "r"(a0[mi][3]),
                          "r"(w10), "r"(w11));
                }
            }
        }
        __syncthreads();
    }

    #pragma unroll
    for (int mi = 0; mi < 2; mi++) {
        #pragma unroll
        for (int ni = 0; ni < 8; ni++) {
            int col = bn + wn*64 + ni*8 + lc;
            float b0 = bias[col], b1 = bias[col + 1];
            int row0 = bm + wm*32 + mi*16 + lr;
            *(float2*)(g_proj + (size_t)row0 * N3 + col) =
                make_float2(acc[mi][ni][0] + b0, acc[mi][ni][1] + b1);
            *(float2*)(g_proj + (size_t)(row0 + 8) * N3 + col) =
                make_float2(acc[mi][ni][2] + b0, acc[mi][ni][3] + b1);
        }
    }
}

// ---------------------------------------------------------------------------
// LIF over t on fast proj; flag neurons with any |h - 1| < DELTA for exact
// recompute. One thread per (lb, f) neuron.
// ---------------------------------------------------------------------------
__global__ __launch_bounds__(256) void lif_flag_kernel()
{
    size_t i = (size_t)blockIdx.x * 256 + threadIdx.x;   // over LB*N3
    float v = 0.f;
    bool flag = false;
    #pragma unroll
    for (int t = 0; t < Tt; t++) {
        float x = g_proj[(size_t)t * LB * N3 + i];
        float h = v + (x - v) * 0.5f;
        flag |= fabsf(h - 1.0f) < DELTA;
        bool s = (h - 1.0f) >= 0.f;
        g_spk[(size_t)t * LB * N3 + i] = s ? 1 : 0;
        v = s ? 0.f : h;
    }
    if (flag) {
        unsigned int p = atomicAdd(&g_nflag, 1u);
        if (p < FIX_CAP) g_list[p] = (unsigned int)i;
    }
}

// ---------------------------------------------------------------------------
// Exact fixup: recompute flagged neurons with sequential-K fp32 FMA
// (bitwise-reference order), rerun LIF, overwrite spikes.
// ---------------------------------------------------------------------------
__global__ __launch_bounds__(256) void fixup_kernel(
    const float* __restrict__ Q, const float* __restrict__ W,
    const float* __restrict__ bias)
{
    unsigned int tid = blockIdx.x * 256 + threadIdx.x;
    unsigned int n = g_nflag; if (n > FIX_CAP) n = FIX_CAP;
    if (tid >= n) return;
    unsigned int i = g_list[tid];
    int lb = i / N3;
    int f  = i - lb * N3;

    const float* wr = W + (size_t)f * Ee;
    float acc[4] = {0.f, 0.f, 0.f, 0.f};
    for (int k = 0; k < Ee; k += 4) {
        float4 wv = *(const float4*)(wr + k);
        #pragma unroll
        for (int t = 0; t < Tt; t++) {
            const float* qr = Q + ((size_t)t * LB + lb) * Ee + k;
            float4 qv = *(const float4*)qr;
            acc[t] = fmaf(qv.x, wv.x, acc[t]);
            acc[t] = fmaf(qv.y, wv.y, acc[t]);
            acc[t] = fmaf(qv.z, wv.z, acc[t]);
            acc[t] = fmaf(qv.w, wv.w, acc[t]);
        }
    }
    float b = bias[f];
    float v = 0.f;
    #pragma unroll
    for (int t = 0; t < Tt; t++) {
        float x = acc[t] + b;
        float h = v + (x - v) * 0.5f;
        bool s = (h - 1.0f) >= 0.f;
        g_spk[(size_t)t * LB * N3 + i] = s ? 1 : 0;
        v = s ? 0.f : h;
    }
}

__global__ __launch_bounds__(256) void zero_attn_kernel()
{
    int i = blockIdx.x * 256 + threadIdx.x;
    g_attn[i] = 0.f;
}

// ---------------------------------------------------------------------------
// attn[t,n,d,e] = sum_l k[t,n,l,d] * v[t,n,l,e]  (binary -> exact counts)
// ---------------------------------------------------------------------------
__global__ __launch_bounds__(256) void kv_attn_kernel()
{
    const int t = blockIdx.z, n = blockIdx.y, ls = blockIdx.x;
    const int b = n >> 3, h = n & 7;
    __shared__ float ks[32][64];
    __shared__ float vs[32][64];
    const int tx = threadIdx.x & 15, ty = threadIdx.x >> 4;

    float acc[4][4];
    #pragma unroll
    for (int i = 0; i < 4; i++)
        #pragma unroll
        for (int j = 0; j < 4; j++) acc[i][j] = 0.f;

    for (int l0 = ls * 256; l0 < ls * 256 + 256; l0 += 32) {
        for (int i = threadIdx.x; i < 512; i += 256) {
            int ll = i >> 4, d4 = (i & 15) << 2;
            size_t base = ((size_t)t * LB + (size_t)(l0 + ll) * Bb + b) * N3 + h * 64 + d4;
            uchar4 kc = *(const uchar4*)(g_spk + base + 512);
            uchar4 vc = *(const uchar4*)(g_spk + base + 1024);
            *(float4*)&ks[ll][d4] = make_float4(kc.x, kc.y, kc.z, kc.w);
            *(float4*)&vs[ll][d4] = make_float4(vc.x, vc.y, vc.z, vc.w);
        }
        __syncthreads();
        #pragma unroll 8
        for (int ll = 0; ll < 32; ll++) {
            float ka[4], va[4];
            #pragma unroll
            for (int i = 0; i < 4; i++) ka[i] = ks[ll][ty*4 + i];
            #pragma unroll
            for (int j = 0; j < 4; j++) va[j] = vs[ll][tx*4 + j];
            #pragma unroll
            for (int i = 0; i < 4; i++)
                #pragma unroll
                for (int j = 0; j < 4; j++) acc[i][j] += ka[i] * va[j];
        }
        __syncthreads();
    }

    float* ap = g_attn + (size_t)(t * 64 + n) * 64 * 64;
    #pragma unroll
    for (int i = 0; i < 4; i++)
        #pragma unroll
        for (int j = 0; j < 4; j++)
            atomicAdd(ap + (ty*4 + i) * 64 + tx*4 + j, acc[i][j]);
}

// ---------------------------------------------------------------------------
// out = (q @ attn) * 0.125 -> LIF(0.5) over t, fused. Exact integer math.
// ---------------------------------------------------------------------------
__global__ __launch_bounds__(256) void qattn_lif_kernel()
{
    const int n = blockIdx.y, lt = blockIdx.x;
    const int b = n >> 3, h = n & 7;
    __shared__ float   at[64][64];
    __shared__ uint8_t qs[64][64];
    const int e = threadIdx.x & 63, lr = threadIdx.x >> 6;

    float vmem[16];
    #pragma unroll
    for (int i = 0; i < 16; i++) vmem[i] = 0.f;

    for (int t = 0; t < Tt; t++) {
        __syncthreads();
        for (int i = threadIdx.x; i < 4096; i += 256)
            at[i >> 6][i & 63] = g_attn[(size_t)(t * 64 + n) * 4096 + i];
        for (int i = threadIdx.x; i < 1024; i += 256) {
            int ll = i >> 4, d4 = (i & 15) << 2;
            size_t base = ((size_t)t * LB + (size_t)(lt * 64 + ll) * Bb + b) * N3 + h * 64 + d4;
            *(uchar4*)&qs[ll][d4] = *(const uchar4*)(g_spk + base);
        }
        __syncthreads();

        #pragma unroll
        for (int li = 0; li < 16; li++) {
            int llocal = li * 4 + lr;
            float s = 0.f;
            #pragma unroll
            for (int d = 0; d < 64; d++)
                s += (float)qs[llocal][d] * at[d][e];
            float x = s * 0.125f;
            float hh = vmem[li] + (x - vmem[li]) * 0.5f;
            bool sp = (hh - 0.5f) >= 0.f;
            int l = lt * 64 + llocal;
            g_s2[(((size_t)t * Ll + l) * Bb + b) * Ee + h * 64 + e] =
                __float2bfloat16(sp ? 1.f : 0.f);
            vmem[li] = sp ? 0.f : hh;
        }
    }
}

// ---------------------------------------------------------------------------
// Split W_out into bf16 hi + lo
// ---------------------------------------------------------------------------
__global__ __launch_bounds__(256) void wsplit_kernel(const float* __restrict__ W)
{
    int i = blockIdx.x * 256 + threadIdx.x;
    float w = W[i];
    __nv_bfloat16 hi = __float2bfloat16(w);
    g_whi[i] = hi;
    g_wlo[i] = __float2bfloat16(w - __bfloat162float(hi));
}

// ---------------------------------------------------------------------------
// GEMM5: out = s2 @ (Whi + Wlo)^T + bias  (unchanged from R3, verified)
// ---------------------------------------------------------------------------
__global__ __launch_bounds__(256) void gemm5_mma_kernel(
    const float* __restrict__ bias, float* __restrict__ C)
{
    __shared__ __nv_bfloat16 As [128][40];
    __shared__ __nv_bfloat16 Bhi[128][40];
    __shared__ __nv_bfloat16 Blo[128][40];

    const int bm = blockIdx.y * 128;
    const int bn = blockIdx.x * 128;
    const int tid  = threadIdx.x;
    const int wid  = tid >> 5;
    const int lane = tid & 31;
    const int wm = wid >> 1;
    const int wn = wid & 1;
    const int lr = lane >> 2;
    const int lc = (lane & 3) * 2;

    float acc[2][8][4];
    #pragma unroll
    for (int mi = 0; mi < 2; mi++)
        #pragma unroll
        for (int ni = 0; ni < 8; ni++)
            #pragma unroll
            for (int r = 0; r < 4; r++) acc[mi][ni][r] = 0.f;

    for (int k0 = 0; k0 < Ee; k0 += 32) {
        for (int i = tid; i < 512; i += 256) {
            int row = i >> 2, c8 = (i & 3) << 3;
            *(uint4*)&As[row][c8] =
                *(const uint4*)(g_s2 + (size_t)(bm + row) * Ee + k0 + c8);
        }
        for (int i = tid; i < 512; i += 256) {
            int row = i >> 2, c8 = (i & 3) << 3;
            size_t off = (size_t)(bn + row) * Ee + k0 + c8;
            *(uint4*)&Bhi[row][c8] = *(const uint4*)(g_whi + off);
            *(uint4*)&Blo[row][c8] = *(const uint4*)(g_wlo + off);
        }
        __syncthreads();

        #pragma unroll
        for (int kk = 0; kk < 32; kk += 16) {
            uint32_t a[2][4];
            #pragma unroll
            for (int mi = 0; mi < 2; mi++) {
                int rbase = wm*32 + mi*16;
                a[mi][0] = *(const uint32_t*)&As[rbase + lr    ][kk + lc    ];
                a[mi][1] = *(const uint32_t*)&As[rbase + lr + 8][kk + lc    ];
                a[mi][2] = *(const uint32_t*)&As[rbase + lr    ][kk + lc + 8];
                a[mi][3] = *(const uint32_t*)&As[rbase + lr + 8][kk + lc + 8];
            }
            #pragma unroll
            for (int ni = 0; ni < 8; ni++) {
                int nrow = wn*64 + ni*8 + lr;
                uint32_t bh0 = *(const uint32_t*)&Bhi[nrow][kk + lc];
                uint32_t bh1 = *(const uint32_t*)&Bhi[nrow][kk + lc + 8];
                uint32_t bl0 = *(const uint32_t*)&Blo[nrow][kk + lc];
                uint32_t bl1 = *(const uint32_t*)&Blo[nrow][kk + lc + 8];
                #pragma unroll
                for (int mi = 0; mi < 2; mi++) {
                    asm volatile(
                        "mma.sync.aligned.m16n8k16.row.col.f32.bf16.bf16.f32 "
                        "{%0,%1,%2,%3}, {%4,%5,%6,%7}, {%8,%9}, {%0,%1,%2,%3};"
                        : "+f"(acc[mi][ni][0]), "+f"(acc[mi][ni][1]),
                          "+f"(acc[mi][ni][2]), "+f"(acc[mi][ni][3])
                        : "r"(a[mi][0]), "r"(a[mi][1]), "r"(a[mi][2]), "r"(a[mi][3]),
                          "r"(bh0), "r"(bh1));
                    asm volatile(
                        "mma.sync.aligned.m16n8k16.row.col.f32.bf16.bf16.f32 "
                        "{%0,%1,%2,%3}, {%4,%5,%6,%7}, {%8,%9}, {%0,%1,%2,%3};"
                        : "+f"(acc[mi][ni][0]), "+f"(acc[mi][ni][1]),
                          "+f"(acc[mi][ni][2]), "+f"(acc[mi][ni][3])
                        : "r"(a[mi][0]), "r"(a[mi][1]), "r"(a[mi][2]), "r"(a[mi][3]),
                          "r"(bl0), "r"(bl1));
                }
            }
        }
        __syncthreads();
    }

    #pragma unroll
    for (int mi = 0; mi < 2; mi++) {
        #pragma unroll
        for (int ni = 0; ni < 8; ni++) {
            int col = bn + wn*64 + ni*8 + lc;
            float b0 = bias[col], b1 = bias[col + 1];
            int row0 = bm + wm*32 + mi*16 + lr;
            *(float2*)(C + (size_t)row0 * Ee + col) =
                make_float2(acc[mi][ni][0] + b0, acc[mi][ni][1] + b1);
            *(float2*)(C + (size_t)(row0 + 8) * Ee + col) =
                make_float2(acc[mi][ni][2] + b0, acc[mi][ni][3] + b1);
        }
    }
}

// ---------------------------------------------------------------------------
extern "C" void kernel_launch(void* const* d_in, const int* in_sizes, int n_in,
                              void* d_out, int out_size)
{
    const float* query = (const float*)d_in[0];   // (T,L,B,E)
    const float* w_in  = (const float*)d_in[1];   // (3E, E)
    const float* b_in  = (const float*)d_in[2];   // (3E)
    const float* w_out = (const float*)d_in[3];   // (E, E)
    const float* b_out = (const float*)d_in[4];   // (E)
    float* out = (float*)d_out;                   // (T,L,B,E)

    void *p_a0, *p_a1, *p_w0, *p_w1;
    cudaGetSymbolAddress(&p_a0, g_a0);
    cudaGetSymbolAddress(&p_a1, g_a1);
    cudaGetSymbolAddress(&p_w0, g_w0);
    cudaGetSymbolAddress(&p_w1, g_w1);

    // 0) zero flag counter + bf16 splits
    zero_flag_kernel<<<1, 1>>>();
    split_kernel<<<((size_t)Mm * Ee / 4) / 256, 256>>>(
        query, (__nv_bfloat16*)p_a0, (__nv_bfloat16*)p_a1);
    split_kernel<<<((size_t)N3 * Ee / 4) / 256, 256>>>(
        w_in, (__nv_bfloat16*)p_w0, (__nv_bfloat16*)p_w1);
    wsplit_kernel<<<(Ee * Ee) / 256, 256>>>(w_out);

    // 1) fast proj on tensor cores
    gemm1_fast_kernel<<<dim3(N3 / 128, Mm / 128), 256>>>(b_in);

    // 2) LIF + flag marginal neurons, then exact fixup of flagged
    lif_flag_kernel<<<((size_t)LB * N3) / 256, 256>>>();
    fixup_kernel<<<FIX_CAP / 256, 256>>>(query, w_in, b_in);

    // 3) attn = k^T v per (t, head)
    zero_attn_kernel<<<(Tt * 64 * 64 * 64) / 256, 256>>>();
    kv_attn_kernel<<<dim3(8, 64, Tt), 256>>>();

    // 4) out = q @ attn * 0.125 -> LIF(0.5) -> s2 spikes (bf16)
    qattn_lif_kernel<<<dim3(Ll / 64, 64), 256>>>();

    // 5) final = s2 @ W_out^T + b_out on tensor cores
    gemm5_mma_kernel<<<dim3(Ee / 128, Mm / 128), 256>>>(b_out, out);
}